// round 2
// baseline (speedup 1.0000x reference)
#include <cuda_runtime.h>

#define NN 100000
#define NE 1600000
#define NBLK ((NN + 255) / 256)   // 391 blocks of 256 over nodes

// ---------------- static device scratch (allocation-free) ----------------
__device__ int   g_cnt[NN];
__device__ int   g_rowptr[NN + 1];
__device__ int   g_cursor[NN];
__device__ int   g_colidx[NE];
__device__ float g_deginv[NN];
__device__ float g_Y[(size_t)NN * 128];   // GEMM output: [N, 2*fout] (ys | yn)
__device__ float g_H[(size_t)NN * 64];    // hidden activations (pre-BN)
__device__ float g_s1[64];
__device__ float g_s2[64];
__device__ float g_aff[128];              // a[0..64), c[64..128)
__device__ int   g_bsum[512];
__device__ int   g_boff[512];

// packed f32x2 FMA: d = a*b + d (2 FMAs per fma-pipe issue on sm_103a)
__device__ __forceinline__ void fma2(unsigned long long& d,
                                     unsigned long long a,
                                     unsigned long long b) {
    asm("fma.rn.f32x2 %0, %1, %2, %0;" : "+l"(d) : "l"(a), "l"(b));
}
__device__ __forceinline__ float2 u2f2(unsigned long long v) {
    float2 f;
    asm("mov.b64 {%0, %1}, %2;" : "=f"(f.x), "=f"(f.y) : "l"(v));
    return f;
}

// ---------------- CSR build ----------------
__global__ void k_init() {
    int i = blockIdx.x * 256 + threadIdx.x;
    if (i < NN) g_cnt[i] = 0;
    if (i < 64) { g_s1[i] = 0.f; g_s2[i] = 0.f; }
}

__global__ void k_hist(const int* __restrict__ dst) {
    int e = blockIdx.x * 256 + threadIdx.x;
    if (e < NE) atomicAdd(&g_cnt[dst[e]], 1);
}

__global__ void k_scan_block() {
    __shared__ int sh[256];
    int i = blockIdx.x * 256 + threadIdx.x;
    int v = (i < NN) ? g_cnt[i] : 0;
    sh[threadIdx.x] = v;
    __syncthreads();
    #pragma unroll
    for (int off = 1; off < 256; off <<= 1) {
        int t = (threadIdx.x >= off) ? sh[threadIdx.x - off] : 0;
        __syncthreads();
        sh[threadIdx.x] += t;
        __syncthreads();
    }
    if (i < NN) g_rowptr[i] = sh[threadIdx.x] - v;   // block-local exclusive
    if (threadIdx.x == 255) g_bsum[blockIdx.x] = sh[255];
}

__global__ void k_scan_tops(int nb) {
    __shared__ int sh[512];
    int t = threadIdx.x;
    int v = (t < nb) ? g_bsum[t] : 0;
    sh[t] = v;
    __syncthreads();
    #pragma unroll
    for (int off = 1; off < 512; off <<= 1) {
        int tt = (t >= off) ? sh[t - off] : 0;
        __syncthreads();
        sh[t] += tt;
        __syncthreads();
    }
    g_boff[t] = sh[t] - v;   // exclusive
}

__global__ void k_scan_add() {
    int i = blockIdx.x * 256 + threadIdx.x;
    if (i < NN) {
        int rp = g_rowptr[i] + g_boff[blockIdx.x];
        g_rowptr[i] = rp;
        g_cursor[i] = rp;
        int c = g_cnt[i];
        g_deginv[i] = 1.0f / (float)(c > 1 ? c : 1);
    }
    if (blockIdx.x == 0 && threadIdx.x == 0) g_rowptr[NN] = NE;
}

__global__ void k_fill(const int* __restrict__ src, const int* __restrict__ dst) {
    int e = blockIdx.x * 256 + threadIdx.x;
    if (e < NE) {
        int d = dst[e];
        int p = atomicAdd(&g_cursor[d], 1);
        g_colidx[p] = src[e];
    }
}

// ---------------- fused GEMM (f32x2 packed): C[M,NC] = A[M,K] @ [Ws | Wn] ---
// Accumulators packed along TN (column pairs).
//   - B pairs: natural 8B loads from a permuted tile Bt[kk][u][tx][2]
//     (per-warp addresses are 8B-contiguous -> conflict-free LDS.64)
//   - A dup pairs (a,a): duplicated tile Atd, address depends only on ty
//     (2-4 values per warp -> broadcast, conflict-free)
template <int K, int NC, int BM, int TM, int TN, int NT, bool AFF, bool RELU>
__global__ __launch_bounds__(NT) void k_gemm2(
    const float* __restrict__ A,
    const float* __restrict__ Ws, const float* __restrict__ Wn,
    float* __restrict__ C, int M)
{
    constexpr int BK = 16;
    constexpr int F  = NC / 2;
    constexpr int CG = NC / TN;     // threads along columns
    constexpr int NP = TN / 2;      // column pairs per thread
    typedef unsigned long long ull;

    __shared__ __align__(16) float Bt[BK][NP][CG][2];  // BK*NC floats, permuted
    __shared__ __align__(16) float Atd[BK][2 * BM];    // duplicated A tile

    const int tid  = threadIdx.x;
    const int tx   = tid % CG;
    const int ty   = tid / CG;
    const int row0 = blockIdx.x * BM;

    ull acc[TM][NP];
    #pragma unroll
    for (int i = 0; i < TM; i++)
        #pragma unroll
        for (int u = 0; u < NP; u++) acc[i][u] = 0ull;

    for (int k0 = 0; k0 < K; k0 += BK) {
        // weight tile -> permuted pair layout
        #pragma unroll
        for (int idx = tid; idx < BK * NC; idx += NT) {
            int kk = idx / NC, c = idx % NC;
            int kg = k0 + kk;
            float w = (c < F) ? Ws[kg * F + c] : Wn[kg * F + (c - F)];
            Bt[kk][(c % TN) >> 1][c / TN][c & 1] = w;
        }
        // A tile -> duplicated, with optional BN affine + relu
        #pragma unroll
        for (int idx = tid; idx < BM * BK; idx += NT) {
            int r = idx / BK, kk = idx % BK;
            int row = row0 + r, kg = k0 + kk;
            float v = (row < M) ? A[(size_t)row * K + kg] : 0.f;
            if (AFF) {
                v = fmaf(v, g_aff[kg], g_aff[64 + kg]);
                if (RELU) v = fmaxf(v, 0.f);
            }
            float2 vv; vv.x = v; vv.y = v;
            *(float2*)&Atd[kk][2 * r] = vv;
        }
        __syncthreads();
        #pragma unroll
        for (int kk = 0; kk < BK; kk++) {
            ull ad[TM], bp[NP];
            #pragma unroll
            for (int i = 0; i < TM; i++)
                ad[i] = *(const ull*)&Atd[kk][2 * (ty * TM + i)];
            #pragma unroll
            for (int u = 0; u < NP; u++)
                bp[u] = *(const ull*)&Bt[kk][u][tx][0];
            #pragma unroll
            for (int i = 0; i < TM; i++)
                #pragma unroll
                for (int u = 0; u < NP; u++)
                    fma2(acc[i][u], ad[i], bp[u]);
        }
        __syncthreads();
    }

    #pragma unroll
    for (int i = 0; i < TM; i++) {
        int row = row0 + ty * TM + i;
        if (row < M) {
            #pragma unroll
            for (int u = 0; u < NP; u += 2) {
                float2 lo = u2f2(acc[i][u]);
                float2 hi = u2f2(acc[i][u + 1]);
                float4 v4 = make_float4(lo.x, lo.y, hi.x, hi.y);
                *(float4*)(C + (size_t)row * NC + tx * TN + 2 * u) = v4;
            }
        }
    }
}

// ---------------- CSR mean-aggregation + self + bias + BN stats (F=64) -----
__global__ void k_agg64(const float* __restrict__ Y, const float* __restrict__ bias,
                        float* __restrict__ H, int M)
{
    __shared__ float ss[128];   // [0,64): sum, [64,128): sumsq
    int tid = threadIdx.x;
    if (tid < 128) ss[tid] = 0.f;
    __syncthreads();

    int lane = tid & 31, w = tid >> 5;
    int c0 = lane * 2;
    float bx = bias[c0], by = bias[c0 + 1];
    float p1 = 0.f, p2 = 0.f, q1 = 0.f, q2 = 0.f;

    for (int v = blockIdx.x * 8 + w; v < M; v += gridDim.x * 8) {
        int beg = g_rowptr[v], end = g_rowptr[v + 1];
        float ax = 0.f, ay = 0.f;
        for (int e = beg; e < end; e++) {
            int s = g_colidx[e];
            float2 t = *(const float2*)(Y + (size_t)s * 128 + 64 + c0);
            ax += t.x;
            ay += t.y;
        }
        float di = g_deginv[v];
        float2 ys = *(const float2*)(Y + (size_t)v * 128 + c0);
        float hx = fmaf(ax, di, ys.x) + bx;
        float hy = fmaf(ay, di, ys.y) + by;
        float2 hv; hv.x = hx; hv.y = hy;
        *(float2*)(H + (size_t)v * 64 + c0) = hv;
        p1 += hx; p2 += hx * hx;
        q1 += hy; q2 += hy * hy;
    }
    atomicAdd(&ss[c0], p1);      atomicAdd(&ss[64 + c0], p2);
    atomicAdd(&ss[c0 + 1], q1);  atomicAdd(&ss[64 + c0 + 1], q2);
    __syncthreads();
    if (tid < 64) {
        atomicAdd(&g_s1[tid], ss[tid]);
        atomicAdd(&g_s2[tid], ss[64 + tid]);
    }
}

// ---------------- final layer aggregation (F=16, Y stride 32, no BN) -------
__global__ void k_agg16(const float* __restrict__ Y, const float* __restrict__ bias,
                        float* __restrict__ O, int M)
{
    int tid = threadIdx.x, lane = tid & 31, w = tid >> 5;
    bool act = lane < 16;
    float b = act ? bias[lane] : 0.f;
    for (int v = blockIdx.x * 8 + w; v < M; v += gridDim.x * 8) {
        int beg = g_rowptr[v], end = g_rowptr[v + 1];
        float a = 0.f;
        for (int e = beg; e < end; e++) {
            int s = g_colidx[e];
            if (act) a += Y[(size_t)s * 32 + 16 + lane];
        }
        if (act) {
            float ys = Y[(size_t)v * 32 + lane];
            O[(size_t)v * 16 + lane] = fmaf(a, g_deginv[v], ys) + b;
        }
    }
}

// ---------------- BN finalize: build affine for next layer's GEMM loads ----
__global__ void k_bnfinal(const float* __restrict__ g, const float* __restrict__ be,
                          float invN)
{
    int t = threadIdx.x;   // 64 threads
    float m   = g_s1[t] * invN;
    float var = g_s2[t] * invN - m * m;
    float r   = rsqrtf(var + 1e-5f);
    float a   = r * g[t];
    g_aff[t]      = a;
    g_aff[64 + t] = fmaf(-m, a, be[t]);
    g_s1[t] = 0.f;
    g_s2[t] = 0.f;
}

// ---------------- launch ----------------
extern "C" void kernel_launch(void* const* d_in, const int* in_sizes, int n_in,
                              void* d_out, int out_size)
{
    const float* x   = (const float*)d_in[0];
    const int*   src = (const int*)d_in[1];
    const int*   dst = (const int*)d_in[2];
    const float* Ws1 = (const float*)d_in[3];
    const float* Wn1 = (const float*)d_in[4];
    const float* b1  = (const float*)d_in[5];
    const float* g1  = (const float*)d_in[6];
    const float* be1 = (const float*)d_in[7];
    const float* Ws2 = (const float*)d_in[8];
    const float* Wn2 = (const float*)d_in[9];
    const float* b2  = (const float*)d_in[10];
    const float* g2  = (const float*)d_in[11];
    const float* be2 = (const float*)d_in[12];
    const float* Ws3 = (const float*)d_in[13];
    const float* Wn3 = (const float*)d_in[14];
    const float* b3  = (const float*)d_in[15];
    const float* g3  = (const float*)d_in[16];
    const float* be3 = (const float*)d_in[17];
    const float* Ws4 = (const float*)d_in[18];
    const float* Wn4 = (const float*)d_in[19];
    const float* b4  = (const float*)d_in[20];
    float* out = (float*)d_out;

    float *Yp, *Hp;
    cudaGetSymbolAddress((void**)&Yp, g_Y);
    cudaGetSymbolAddress((void**)&Hp, g_H);

    const int EB = (NE + 255) / 256;
    const int GB = (NN + 127) / 128;     // GEMM row blocks (782)
    const int AGG_GRID = 1184;           // 8 warps/block, grid-stride over nodes
    const float invN = 1.0f / (float)NN;

    // build CSC (dst-grouped) once per launch
    k_init<<<NBLK, 256>>>();
    k_hist<<<EB, 256>>>(dst);
    k_scan_block<<<NBLK, 256>>>();
    k_scan_tops<<<1, 512>>>(NBLK);
    k_scan_add<<<NBLK, 256>>>();
    k_fill<<<EB, 256>>>(src, dst);

    // layer 1: SAGE(128->64) + BN (affine deferred to layer-2 GEMM loads)
    k_gemm2<128, 128, 128, 8, 8, 256, false, false><<<GB, 256>>>(x, Ws1, Wn1, Yp, NN);
    k_agg64<<<AGG_GRID, 256>>>(Yp, b1, Hp, NN);
    k_bnfinal<<<1, 64>>>(g1, be1, invN);

    // layer 2: SAGE(64->64) + BN; input = BN1(h1), no relu
    k_gemm2<64, 128, 128, 8, 8, 256, true, false><<<GB, 256>>>(Hp, Ws2, Wn2, Yp, NN);
    k_agg64<<<AGG_GRID, 256>>>(Yp, b2, Hp, NN);
    k_bnfinal<<<1, 64>>>(g2, be2, invN);

    // layer 3: input = relu(BN2(h2))
    k_gemm2<64, 128, 128, 8, 8, 256, true, true><<<GB, 256>>>(Hp, Ws3, Wn3, Yp, NN);
    k_agg64<<<AGG_GRID, 256>>>(Yp, b3, Hp, NN);
    k_bnfinal<<<1, 64>>>(g3, be3, invN);

    // layer 4: SAGE(64->16), input = relu(BN3(h3)), output straight to d_out
    k_gemm2<64, 32, 128, 8, 4, 128, true, true><<<GB, 128>>>(Hp, Ws4, Wn4, Yp, NN);
    k_agg16<<<AGG_GRID, 256>>>(Yp, b4, out, NN);
}

// round 4
// speedup vs baseline: 1.8854x; 1.8854x over previous
#include <cuda_runtime.h>
#include <cuda_bf16.h>
#include <cstdint>

#define NN 100000
#define NE 1600000
#define NBLK ((NN + 255) / 256)

// ---------------- static device scratch (allocation-free) ----------------
__device__ int   g_cnt[NN];
__device__ int   g_rowptr[NN + 1];
__device__ int   g_cursor[NN];
__device__ int   g_colidx[NE];
__device__ float g_deginv[NN];
__device__ float g_Y[(size_t)NN * 128];   // GEMM output: [N, 2*fout] (ys | yn)
__device__ float g_H[(size_t)NN * 64];    // hidden activations (pre-BN)
__device__ float g_s1[64];
__device__ float g_s2[64];
__device__ float g_aff[128];              // a[0..64), c[64..128)
__device__ int   g_bsum[512];
__device__ int   g_boff[512];
__device__ uint4 g_Bf[4096];              // packed B fragments (max: KS8*NT16*32)

// ---------------- helpers ----------------
// split (v0,v1) into bf16 hi pair + bf16 lo (residual) pair, packed u32
__device__ __forceinline__ void split2(float v0, float v1,
                                       uint32_t& h, uint32_t& l) {
    __nv_bfloat162 hp = __floats2bfloat162_rn(v0, v1);
    float r0 = v0 - __low2float(hp);
    float r1 = v1 - __high2float(hp);
    __nv_bfloat162 lp = __floats2bfloat162_rn(r0, r1);
    h = *(uint32_t*)&hp;
    l = *(uint32_t*)&lp;
}

// m16n8k16 bf16 MMA, fp32 accumulate (warp-level, sm_80+ encoding)
__device__ __forceinline__ void mma_bf16(float* c, const uint4& a,
                                         uint32_t b0, uint32_t b1) {
    asm volatile(
        "mma.sync.aligned.m16n8k16.row.col.f32.bf16.bf16.f32 "
        "{%0,%1,%2,%3}, {%4,%5,%6,%7}, {%8,%9}, {%0,%1,%2,%3};"
        : "+f"(c[0]), "+f"(c[1]), "+f"(c[2]), "+f"(c[3])
        : "r"(a.x), "r"(a.y), "r"(a.z), "r"(a.w), "r"(b0), "r"(b1));
}

// ---------------- CSR build ----------------
__global__ void k_init() {
    int i = blockIdx.x * 256 + threadIdx.x;
    if (i < NN) g_cnt[i] = 0;
    if (i < 64) { g_s1[i] = 0.f; g_s2[i] = 0.f; }
}

__global__ void k_hist(const int* __restrict__ dst) {
    int e = blockIdx.x * 256 + threadIdx.x;
    if (e < NE) atomicAdd(&g_cnt[dst[e]], 1);
}

__global__ void k_scan_block() {
    __shared__ int sh[256];
    int i = blockIdx.x * 256 + threadIdx.x;
    int v = (i < NN) ? g_cnt[i] : 0;
    sh[threadIdx.x] = v;
    __syncthreads();
    #pragma unroll
    for (int off = 1; off < 256; off <<= 1) {
        int t = (threadIdx.x >= off) ? sh[threadIdx.x - off] : 0;
        __syncthreads();
        sh[threadIdx.x] += t;
        __syncthreads();
    }
    if (i < NN) g_rowptr[i] = sh[threadIdx.x] - v;
    if (threadIdx.x == 255) g_bsum[blockIdx.x] = sh[255];
}

__global__ void k_scan_tops(int nb) {
    __shared__ int sh[512];
    int t = threadIdx.x;
    int v = (t < nb) ? g_bsum[t] : 0;
    sh[t] = v;
    __syncthreads();
    #pragma unroll
    for (int off = 1; off < 512; off <<= 1) {
        int tt = (t >= off) ? sh[t - off] : 0;
        __syncthreads();
        sh[t] += tt;
        __syncthreads();
    }
    g_boff[t] = sh[t] - v;
}

__global__ void k_scan_add() {
    int i = blockIdx.x * 256 + threadIdx.x;
    if (i < NN) {
        int rp = g_rowptr[i] + g_boff[blockIdx.x];
        g_rowptr[i] = rp;
        g_cursor[i] = rp;
        int c = g_cnt[i];
        g_deginv[i] = 1.0f / (float)(c > 1 ? c : 1);
    }
    if (blockIdx.x == 0 && threadIdx.x == 0) g_rowptr[NN] = NE;
}

__global__ void k_fill(const int* __restrict__ src, const int* __restrict__ dst) {
    int e = blockIdx.x * 256 + threadIdx.x;
    if (e < NE) {
        int d = dst[e];
        int p = atomicAdd(&g_cursor[d], 1);
        g_colidx[p] = src[e];
    }
}

// ---------------- B fragment pack: W=[Ws|Wn] -> mma col-major fragments ----
// g_Bf[(s*NT+t)*32 + lane] = {bh0, bh1, bl0, bl1}
//   b0: (k = s*16 + 2c + {0,1}, n = t*8 + g);  b1: k += 8.  (c=lane&3, g=lane>>2)
template <int K, int NC>
__global__ void k_bpack(const float* __restrict__ Ws, const float* __restrict__ Wn) {
    constexpr int F = NC / 2, NT = NC / 8;
    constexpr int TOTAL = (K / 16) * NT * 32;
    int i = blockIdx.x * 256 + threadIdx.x;
    if (i >= TOTAL) return;
    int lane = i & 31, t = (i >> 5) % NT, s = (i >> 5) / NT;
    int c = lane & 3, gn = lane >> 2;
    int n = t * 8 + gn;
    int k0 = s * 16 + 2 * c;
    const float* W = (n < F) ? Ws : Wn;
    int nn = (n < F) ? n : n - F;
    float w00 = W[(k0    ) * F + nn];
    float w01 = W[(k0 + 1) * F + nn];
    float w10 = W[(k0 + 8) * F + nn];
    float w11 = W[(k0 + 9) * F + nn];
    uint4 q;
    split2(w00, w01, q.x, q.z);
    split2(w10, w11, q.y, q.w);
    g_Bf[i] = q;
}

// ---------------- MMA GEMM: C[M,NC] = affine(A)[M,K] @ [Ws|Wn] -------------
// 3-pass bf16 hi/lo split, fp32 accumulation. CTA = 128 rows, 8 warps
// (warp w owns rows [w*16, w*16+16)). A staged in smem in fragment order.
template <int K, int NC, bool AFF, bool RELU>
__global__ __launch_bounds__(256) void k_mma(
    const float* __restrict__ A, float* __restrict__ C, int M)
{
    constexpr int KS = K / 16, NT = NC / 8;
    constexpr int ATILES = 8 * KS * 32;
    extern __shared__ uint4 sA[];
    uint4* sH = sA;
    uint4* sL = sA + ATILES;

    const int tid  = threadIdx.x;
    const int row0 = blockIdx.x * 128;

    // ---- stage A fragments (hi/lo), folded BN affine + relu ----
    for (int i = tid; i < ATILES; i += 256) {
        int w  = i / (KS * 32);
        int s  = (i / 32) % KS;
        int ln = i & 31;
        int g = ln >> 2, c = ln & 3;
        int k0 = s * 16 + 2 * c;
        int r0 = row0 + w * 16 + g, r1 = r0 + 8;
        float2 v00 = (r0 < M) ? *(const float2*)(A + (size_t)r0 * K + k0)
                              : make_float2(0.f, 0.f);
        float2 v01 = (r0 < M) ? *(const float2*)(A + (size_t)r0 * K + k0 + 8)
                              : make_float2(0.f, 0.f);
        float2 v10 = (r1 < M) ? *(const float2*)(A + (size_t)r1 * K + k0)
                              : make_float2(0.f, 0.f);
        float2 v11 = (r1 < M) ? *(const float2*)(A + (size_t)r1 * K + k0 + 8)
                              : make_float2(0.f, 0.f);
        if (AFF) {
            float a0 = g_aff[k0],     c0 = g_aff[64 + k0];
            float a1 = g_aff[k0 + 1], c1 = g_aff[64 + k0 + 1];
            float a2 = g_aff[k0 + 8], c2 = g_aff[64 + k0 + 8];
            float a3 = g_aff[k0 + 9], c3 = g_aff[64 + k0 + 9];
            v00.x = fmaf(v00.x, a0, c0); v00.y = fmaf(v00.y, a1, c1);
            v10.x = fmaf(v10.x, a0, c0); v10.y = fmaf(v10.y, a1, c1);
            v01.x = fmaf(v01.x, a2, c2); v01.y = fmaf(v01.y, a3, c3);
            v11.x = fmaf(v11.x, a2, c2); v11.y = fmaf(v11.y, a3, c3);
            if (RELU) {
                v00.x = fmaxf(v00.x, 0.f); v00.y = fmaxf(v00.y, 0.f);
                v01.x = fmaxf(v01.x, 0.f); v01.y = fmaxf(v01.y, 0.f);
                v10.x = fmaxf(v10.x, 0.f); v10.y = fmaxf(v10.y, 0.f);
                v11.x = fmaxf(v11.x, 0.f); v11.y = fmaxf(v11.y, 0.f);
            }
        }
        uint4 hq, lq;
        split2(v00.x, v00.y, hq.x, lq.x);   // a0: row g,   k lo
        split2(v10.x, v10.y, hq.y, lq.y);   // a1: row g+8, k lo
        split2(v01.x, v01.y, hq.z, lq.z);   // a2: row g,   k hi
        split2(v11.x, v11.y, hq.w, lq.w);   // a3: row g+8, k hi
        sH[i] = hq;
        sL[i] = lq;
    }
    __syncthreads();

    const int wid = tid >> 5, lane = tid & 31;
    float acc[NT][4];
    #pragma unroll
    for (int t = 0; t < NT; t++)
        #pragma unroll
        for (int j = 0; j < 4; j++) acc[t][j] = 0.f;

    const uint4* aH = sH + (wid * KS) * 32 + lane;
    const uint4* aL = sL + (wid * KS) * 32 + lane;
    #pragma unroll
    for (int s = 0; s < KS; s++) {
        uint4 ah = aH[s * 32];
        uint4 al = aL[s * 32];
        const uint4* bp = g_Bf + (size_t)s * NT * 32 + lane;
        #pragma unroll
        for (int t = 0; t < NT; t++) {
            uint4 b = bp[t * 32];
            mma_bf16(acc[t], ah, b.x, b.y);   // Ah * Bh
            mma_bf16(acc[t], ah, b.z, b.w);   // Ah * Bl
            mma_bf16(acc[t], al, b.x, b.y);   // Al * Bh
        }
    }

    // ---- epilogue: registers straight to C ----
    int g = lane >> 2, c = lane & 3;
    int r0 = row0 + wid * 16 + g, r1 = r0 + 8;
    #pragma unroll
    for (int t = 0; t < NT; t++) {
        int col = t * 8 + 2 * c;
        if (r0 < M)
            *(float2*)(C + (size_t)r0 * NC + col) = make_float2(acc[t][0], acc[t][1]);
        if (r1 < M)
            *(float2*)(C + (size_t)r1 * NC + col) = make_float2(acc[t][2], acc[t][3]);
    }
}

// ---------------- CSR mean-aggregation + self + bias + BN stats (F=64) -----
__global__ void k_agg64(const float* __restrict__ Y, const float* __restrict__ bias,
                        float* __restrict__ H, int M)
{
    __shared__ float ss[128];
    int tid = threadIdx.x;
    if (tid < 128) ss[tid] = 0.f;
    __syncthreads();

    int lane = tid & 31, w = tid >> 5;
    int c0 = lane * 2;
    float bx = bias[c0], by = bias[c0 + 1];
    float p1 = 0.f, p2 = 0.f, q1 = 0.f, q2 = 0.f;

    for (int v = blockIdx.x * 8 + w; v < M; v += gridDim.x * 8) {
        int beg = g_rowptr[v], end = g_rowptr[v + 1];
        float ax = 0.f, ay = 0.f;
        for (int e = beg; e < end; e++) {
            int s = g_colidx[e];
            float2 t = *(const float2*)(Y + (size_t)s * 128 + 64 + c0);
            ax += t.x;
            ay += t.y;
        }
        float di = g_deginv[v];
        float2 ys = *(const float2*)(Y + (size_t)v * 128 + c0);
        float hx = fmaf(ax, di, ys.x) + bx;
        float hy = fmaf(ay, di, ys.y) + by;
        float2 hv; hv.x = hx; hv.y = hy;
        *(float2*)(H + (size_t)v * 64 + c0) = hv;
        p1 += hx; p2 += hx * hx;
        q1 += hy; q2 += hy * hy;
    }
    atomicAdd(&ss[c0], p1);      atomicAdd(&ss[64 + c0], p2);
    atomicAdd(&ss[c0 + 1], q1);  atomicAdd(&ss[64 + c0 + 1], q2);
    __syncthreads();
    if (tid < 64) {
        atomicAdd(&g_s1[tid], ss[tid]);
        atomicAdd(&g_s2[tid], ss[64 + tid]);
    }
}

// ---------------- final layer aggregation (F=16, Y stride 32, no BN) -------
__global__ void k_agg16(const float* __restrict__ Y, const float* __restrict__ bias,
                        float* __restrict__ O, int M)
{
    int tid = threadIdx.x, lane = tid & 31, w = tid >> 5;
    bool act = lane < 16;
    float b = act ? bias[lane] : 0.f;
    for (int v = blockIdx.x * 8 + w; v < M; v += gridDim.x * 8) {
        int beg = g_rowptr[v], end = g_rowptr[v + 1];
        float a = 0.f;
        for (int e = beg; e < end; e++) {
            int s = g_colidx[e];
            if (act) a += Y[(size_t)s * 32 + 16 + lane];
        }
        if (act) {
            float ys = Y[(size_t)v * 32 + lane];
            O[(size_t)v * 16 + lane] = fmaf(a, g_deginv[v], ys) + b;
        }
    }
}

// ---------------- BN finalize ----------------
__global__ void k_bnfinal(const float* __restrict__ g, const float* __restrict__ be,
                          float invN)
{
    int t = threadIdx.x;
    float m   = g_s1[t] * invN;
    float var = g_s2[t] * invN - m * m;
    float r   = rsqrtf(var + 1e-5f);
    float a   = r * g[t];
    g_aff[t]      = a;
    g_aff[64 + t] = fmaf(-m, a, be[t]);
    g_s1[t] = 0.f;
    g_s2[t] = 0.f;
}

// ---------------- launch ----------------
static constexpr int smem_mma(int K) { return 2 * 8 * (K / 16) * 32 * 16; }

extern "C" void kernel_launch(void* const* d_in, const int* in_sizes, int n_in,
                              void* d_out, int out_size)
{
    const float* x   = (const float*)d_in[0];
    const int*   src = (const int*)d_in[1];
    const int*   dst = (const int*)d_in[2];
    const float* Ws1 = (const float*)d_in[3];
    const float* Wn1 = (const float*)d_in[4];
    const float* b1  = (const float*)d_in[5];
    const float* g1  = (const float*)d_in[6];
    const float* be1 = (const float*)d_in[7];
    const float* Ws2 = (const float*)d_in[8];
    const float* Wn2 = (const float*)d_in[9];
    const float* b2  = (const float*)d_in[10];
    const float* g2  = (const float*)d_in[11];
    const float* be2 = (const float*)d_in[12];
    const float* Ws3 = (const float*)d_in[13];
    const float* Wn3 = (const float*)d_in[14];
    const float* b3  = (const float*)d_in[15];
    const float* g3  = (const float*)d_in[16];
    const float* be3 = (const float*)d_in[17];
    const float* Ws4 = (const float*)d_in[18];
    const float* Wn4 = (const float*)d_in[19];
    const float* b4  = (const float*)d_in[20];
    float* out = (float*)d_out;

    float *Yp, *Hp;
    cudaGetSymbolAddress((void**)&Yp, g_Y);
    cudaGetSymbolAddress((void**)&Hp, g_H);

    const int EB = (NE + 255) / 256;
    const int GB = (NN + 127) / 128;     // 782 row tiles
    const int AGG_GRID = 1184;
    const float invN = 1.0f / (float)NN;

    cudaFuncSetAttribute(k_mma<128, 128, false, false>,
        cudaFuncAttributeMaxDynamicSharedMemorySize, smem_mma(128));
    cudaFuncSetAttribute(k_mma<64, 128, true, false>,
        cudaFuncAttributeMaxDynamicSharedMemorySize, smem_mma(64));
    cudaFuncSetAttribute(k_mma<64, 128, true, true>,
        cudaFuncAttributeMaxDynamicSharedMemorySize, smem_mma(64));
    cudaFuncSetAttribute(k_mma<64, 32, true, true>,
        cudaFuncAttributeMaxDynamicSharedMemorySize, smem_mma(64));

    // build CSC (dst-grouped) once per launch
    k_init<<<NBLK, 256>>>();
    k_hist<<<EB, 256>>>(dst);
    k_scan_block<<<NBLK, 256>>>();
    k_scan_tops<<<1, 512>>>(NBLK);
    k_scan_add<<<NBLK, 256>>>();
    k_fill<<<EB, 256>>>(src, dst);

    // layer 1: SAGE(128->64) + BN (affine deferred to layer-2 GEMM loads)
    k_bpack<128, 128><<<16, 256>>>(Ws1, Wn1);
    k_mma<128, 128, false, false><<<GB, 256, smem_mma(128)>>>(x, Yp, NN);
    k_agg64<<<AGG_GRID, 256>>>(Yp, b1, Hp, NN);
    k_bnfinal<<<1, 64>>>(g1, be1, invN);

    // layer 2: SAGE(64->64) + BN; input = BN1(h1), no relu
    k_bpack<64, 128><<<8, 256>>>(Ws2, Wn2);
    k_mma<64, 128, true, false><<<GB, 256, smem_mma(64)>>>(Hp, Yp, NN);
    k_agg64<<<AGG_GRID, 256>>>(Yp, b2, Hp, NN);
    k_bnfinal<<<1, 64>>>(g2, be2, invN);

    // layer 3: input = relu(BN2(h2))
    k_bpack<64, 128><<<8, 256>>>(Ws3, Wn3);
    k_mma<64, 128, true, true><<<GB, 256, smem_mma(64)>>>(Hp, Yp, NN);
    k_agg64<<<AGG_GRID, 256>>>(Yp, b3, Hp, NN);
    k_bnfinal<<<1, 64>>>(g3, be3, invN);

    // layer 4: SAGE(64->16), input = relu(BN3(h3))
    k_bpack<64, 32><<<2, 256>>>(Ws4, Wn4);
    k_mma<64, 32, true, true><<<GB, 256, smem_mma(64)>>>(Hp, Yp, NN);
    k_agg16<<<AGG_GRID, 256>>>(Yp, b4, out, NN);
}

// round 5
// speedup vs baseline: 1.9036x; 1.0097x over previous
#include <cuda_runtime.h>
#include <cuda_bf16.h>
#include <cuda_fp16.h>
#include <cstdint>

#define NN 100000
#define NE 1600000
#define NBLK ((NN + 255) / 256)

// ---------------- static device scratch (allocation-free) ----------------
__device__ int    g_cnt[NN];
__device__ int    g_rowptr[NN + 1];
__device__ int    g_cursor[NN];
__device__ int    g_colidx[NE];
__device__ float  g_deginv[NN];
__device__ float  g_Ys[(size_t)NN * 64];   // self-term GEMM output (fp32)
__device__ __half g_Yh[(size_t)NN * 64];   // neighbor-term GEMM output (fp16)
__device__ float  g_H[(size_t)NN * 64];    // hidden activations (pre-BN)
__device__ float  g_stat1[192];            // per-layer BN sums (3 x 64)
__device__ float  g_stat2[192];            // per-layer BN sumsq
__device__ int    g_bsum[512];
__device__ int    g_boff[512];
__device__ uint4  g_Bf[8704];              // packed B frags: L1@0, L2@4096, L3@6144, L4@8192

// ---------------- helpers ----------------
__device__ __forceinline__ void split2(float v0, float v1,
                                       uint32_t& h, uint32_t& l) {
    __nv_bfloat162 hp = __floats2bfloat162_rn(v0, v1);
    float r0 = v0 - __low2float(hp);
    float r1 = v1 - __high2float(hp);
    __nv_bfloat162 lp = __floats2bfloat162_rn(r0, r1);
    h = *(uint32_t*)&hp;
    l = *(uint32_t*)&lp;
}

__device__ __forceinline__ void mma_bf16(float* c, const uint4& a,
                                         uint32_t b0, uint32_t b1) {
    asm volatile(
        "mma.sync.aligned.m16n8k16.row.col.f32.bf16.bf16.f32 "
        "{%0,%1,%2,%3}, {%4,%5,%6,%7}, {%8,%9}, {%0,%1,%2,%3};"
        : "+f"(c[0]), "+f"(c[1]), "+f"(c[2]), "+f"(c[3])
        : "r"(a.x), "r"(a.y), "r"(a.z), "r"(a.w), "r"(b0), "r"(b1));
}

// ---------------- CSR build ----------------
__global__ void k_init() {
    int i = blockIdx.x * 256 + threadIdx.x;
    if (i < NN) g_cnt[i] = 0;
    if (i < 192) { g_stat1[i] = 0.f; g_stat2[i] = 0.f; }
}

__global__ void k_hist(const int* __restrict__ dst) {
    int e = blockIdx.x * 256 + threadIdx.x;
    if (e < NE) atomicAdd(&g_cnt[dst[e]], 1);
}

__global__ void k_scan_block() {
    __shared__ int sh[256];
    int i = blockIdx.x * 256 + threadIdx.x;
    int v = (i < NN) ? g_cnt[i] : 0;
    sh[threadIdx.x] = v;
    __syncthreads();
    #pragma unroll
    for (int off = 1; off < 256; off <<= 1) {
        int t = (threadIdx.x >= off) ? sh[threadIdx.x - off] : 0;
        __syncthreads();
        sh[threadIdx.x] += t;
        __syncthreads();
    }
    if (i < NN) g_rowptr[i] = sh[threadIdx.x] - v;
    if (threadIdx.x == 255) g_bsum[blockIdx.x] = sh[255];
}

__global__ void k_scan_tops(int nb) {
    __shared__ int sh[512];
    int t = threadIdx.x;
    int v = (t < nb) ? g_bsum[t] : 0;
    sh[t] = v;
    __syncthreads();
    #pragma unroll
    for (int off = 1; off < 512; off <<= 1) {
        int tt = (t >= off) ? sh[t - off] : 0;
        __syncthreads();
        sh[t] += tt;
        __syncthreads();
    }
    g_boff[t] = sh[t] - v;
}

__global__ void k_scan_add() {
    int i = blockIdx.x * 256 + threadIdx.x;
    if (i < NN) {
        int rp = g_rowptr[i] + g_boff[blockIdx.x];
        g_rowptr[i] = rp;
        g_cursor[i] = rp;
        int c = g_cnt[i];
        g_deginv[i] = 1.0f / (float)(c > 1 ? c : 1);
    }
    if (blockIdx.x == 0 && threadIdx.x == 0) g_rowptr[NN] = NE;
}

__global__ void k_fill(const int* __restrict__ src, const int* __restrict__ dst) {
    int e = blockIdx.x * 256 + threadIdx.x;
    if (e < NE) {
        int d = dst[e];
        int p = atomicAdd(&g_cursor[d], 1);
        g_colidx[p] = src[e];
    }
}

// ---------------- B fragment pack (all 4 layers, one kernel) ----------------
__device__ __forceinline__ void bpack_one(int idx, int base, int K, int NC,
                                          const float* __restrict__ Ws,
                                          const float* __restrict__ Wn) {
    int F = NC / 2, NT = NC / 8;
    int lane = idx & 31, t = (idx >> 5) % NT, s = (idx >> 5) / NT;
    int c = lane & 3, gn = lane >> 2;
    int n = t * 8 + gn;
    int k0 = s * 16 + 2 * c;
    const float* W = (n < F) ? Ws : Wn;
    int nn = (n < F) ? n : n - F;
    float w00 = W[(k0    ) * F + nn];
    float w01 = W[(k0 + 1) * F + nn];
    float w10 = W[(k0 + 8) * F + nn];
    float w11 = W[(k0 + 9) * F + nn];
    uint4 q;
    split2(w00, w01, q.x, q.z);
    split2(w10, w11, q.y, q.w);
    g_Bf[base + idx] = q;
}

__global__ void k_bpack_all(const float* Ws1, const float* Wn1,
                            const float* Ws2, const float* Wn2,
                            const float* Ws3, const float* Wn3,
                            const float* Ws4, const float* Wn4) {
    int i = blockIdx.x * 256 + threadIdx.x;
    if      (i < 4096) bpack_one(i,        0,    128, 128, Ws1, Wn1);
    else if (i < 6144) bpack_one(i - 4096, 4096, 64,  128, Ws2, Wn2);
    else if (i < 8192) bpack_one(i - 6144, 6144, 64,  128, Ws3, Wn3);
    else if (i < 8704) bpack_one(i - 8192, 8192, 64,  32,  Ws4, Wn4);
}

// ---------------- MMA GEMM: [Ys|Yh] = affine(A) @ [Ws|Wn] -------------------
// 3-pass bf16 hi/lo split, fp32 accum. CTA = 128 rows, 8 warps.
// BN affine recomputed per-CTA from per-layer stat slots (replaces k_bnfinal).
// Self half -> fp32 Ys; neighbor half -> fp16 Yh (gathered per-edge later).
template <int K, int NC, bool AFF, bool RELU>
__global__ __launch_bounds__(256) void k_mma(
    const float* __restrict__ A, const uint4* __restrict__ Bf,
    float* __restrict__ Ys, __half* __restrict__ Yh,
    const float* __restrict__ s1, const float* __restrict__ s2,
    const float* __restrict__ gamma, const float* __restrict__ beta,
    int M)
{
    constexpr int KS = K / 16, NT = NC / 8, F = NC / 2;
    constexpr int ATILES = 8 * KS * 32;
    extern __shared__ uint4 sA[];
    uint4* sH = sA;
    uint4* sL = sA + ATILES;
    __shared__ float sAff[128];

    const int tid  = threadIdx.x;
    const int row0 = blockIdx.x * 128;

    if (AFF) {
        if (tid < 64) {
            const float invN = 1.0f / (float)NN;
            float m   = s1[tid] * invN;
            float var = s2[tid] * invN - m * m;
            float r   = rsqrtf(var + 1e-5f);
            float a   = r * gamma[tid];
            sAff[tid]      = a;
            sAff[64 + tid] = fmaf(-m, a, beta[tid]);
        }
        __syncthreads();
    }

    // ---- stage A fragments (hi/lo), folded BN affine + relu ----
    for (int i = tid; i < ATILES; i += 256) {
        int w  = i / (KS * 32);
        int s  = (i / 32) % KS;
        int ln = i & 31;
        int g = ln >> 2, c = ln & 3;
        int k0 = s * 16 + 2 * c;
        int r0 = row0 + w * 16 + g, r1 = r0 + 8;
        float2 v00 = (r0 < M) ? *(const float2*)(A + (size_t)r0 * K + k0)
                              : make_float2(0.f, 0.f);
        float2 v01 = (r0 < M) ? *(const float2*)(A + (size_t)r0 * K + k0 + 8)
                              : make_float2(0.f, 0.f);
        float2 v10 = (r1 < M) ? *(const float2*)(A + (size_t)r1 * K + k0)
                              : make_float2(0.f, 0.f);
        float2 v11 = (r1 < M) ? *(const float2*)(A + (size_t)r1 * K + k0 + 8)
                              : make_float2(0.f, 0.f);
        if (AFF) {
            float a0 = sAff[k0],     c0 = sAff[64 + k0];
            float a1 = sAff[k0 + 1], c1 = sAff[64 + k0 + 1];
            float a2 = sAff[k0 + 8], c2 = sAff[64 + k0 + 8];
            float a3 = sAff[k0 + 9], c3 = sAff[64 + k0 + 9];
            v00.x = fmaf(v00.x, a0, c0); v00.y = fmaf(v00.y, a1, c1);
            v10.x = fmaf(v10.x, a0, c0); v10.y = fmaf(v10.y, a1, c1);
            v01.x = fmaf(v01.x, a2, c2); v01.y = fmaf(v01.y, a3, c3);
            v11.x = fmaf(v11.x, a2, c2); v11.y = fmaf(v11.y, a3, c3);
            if (RELU) {
                v00.x = fmaxf(v00.x, 0.f); v00.y = fmaxf(v00.y, 0.f);
                v01.x = fmaxf(v01.x, 0.f); v01.y = fmaxf(v01.y, 0.f);
                v10.x = fmaxf(v10.x, 0.f); v10.y = fmaxf(v10.y, 0.f);
                v11.x = fmaxf(v11.x, 0.f); v11.y = fmaxf(v11.y, 0.f);
            }
        }
        uint4 hq, lq;
        split2(v00.x, v00.y, hq.x, lq.x);
        split2(v10.x, v10.y, hq.y, lq.y);
        split2(v01.x, v01.y, hq.z, lq.z);
        split2(v11.x, v11.y, hq.w, lq.w);
        sH[i] = hq;
        sL[i] = lq;
    }
    __syncthreads();

    const int wid = tid >> 5, lane = tid & 31;
    float acc[NT][4];
    #pragma unroll
    for (int t = 0; t < NT; t++)
        #pragma unroll
        for (int j = 0; j < 4; j++) acc[t][j] = 0.f;

    const uint4* aH = sH + (wid * KS) * 32 + lane;
    const uint4* aL = sL + (wid * KS) * 32 + lane;
    #pragma unroll
    for (int s = 0; s < KS; s++) {
        uint4 ah = aH[s * 32];
        uint4 al = aL[s * 32];
        const uint4* bp = Bf + (size_t)s * NT * 32 + lane;
        #pragma unroll
        for (int t = 0; t < NT; t++) {
            uint4 b = bp[t * 32];
            mma_bf16(acc[t], ah, b.x, b.y);   // Ah * Bh
            mma_bf16(acc[t], ah, b.z, b.w);   // Ah * Bl
            mma_bf16(acc[t], al, b.x, b.y);   // Al * Bh
        }
    }

    // ---- epilogue: self half -> fp32 Ys, neighbor half -> fp16 Yh ----
    int g = lane >> 2, c = lane & 3;
    int r0 = row0 + wid * 16 + g, r1 = r0 + 8;
    #pragma unroll
    for (int t = 0; t < NT; t++) {
        if (t < NT / 2) {
            int col = t * 8 + 2 * c;
            if (r0 < M)
                *(float2*)(Ys + (size_t)r0 * F + col) = make_float2(acc[t][0], acc[t][1]);
            if (r1 < M)
                *(float2*)(Ys + (size_t)r1 * F + col) = make_float2(acc[t][2], acc[t][3]);
        } else {
            int col = (t - NT / 2) * 8 + 2 * c;
            if (r0 < M)
                *(__half2*)(Yh + (size_t)r0 * F + col) = __floats2half2_rn(acc[t][0], acc[t][1]);
            if (r1 < M)
                *(__half2*)(Yh + (size_t)r1 * F + col) = __floats2half2_rn(acc[t][2], acc[t][3]);
        }
    }
}

// ---------------- CSR mean-agg + self + bias + BN stats (F=64, fp16 gather) -
__global__ void k_agg64(const float* __restrict__ Ys, const __half2* __restrict__ Yh,
                        const float* __restrict__ bias, float* __restrict__ H,
                        float* __restrict__ s1, float* __restrict__ s2, int M)
{
    __shared__ float ss[128];
    int tid = threadIdx.x;
    if (tid < 128) ss[tid] = 0.f;
    __syncthreads();

    int lane = tid & 31, w = tid >> 5;
    int c0 = lane * 2;
    float bx = bias[c0], by = bias[c0 + 1];
    float p1 = 0.f, p2 = 0.f, q1 = 0.f, q2 = 0.f;

    for (int v = blockIdx.x * 8 + w; v < M; v += gridDim.x * 8) {
        int beg = g_rowptr[v], end = g_rowptr[v + 1];
        float ax = 0.f, ay = 0.f;
        for (int e = beg; e < end; e++) {
            int s = g_colidx[e];
            float2 t = __half22float2(Yh[(size_t)s * 32 + lane]);
            ax += t.x;
            ay += t.y;
        }
        float di = g_deginv[v];
        float2 ys = *(const float2*)(Ys + (size_t)v * 64 + c0);
        float hx = fmaf(ax, di, ys.x) + bx;
        float hy = fmaf(ay, di, ys.y) + by;
        *(float2*)(H + (size_t)v * 64 + c0) = make_float2(hx, hy);
        p1 += hx; p2 += hx * hx;
        q1 += hy; q2 += hy * hy;
    }
    atomicAdd(&ss[c0], p1);      atomicAdd(&ss[64 + c0], p2);
    atomicAdd(&ss[c0 + 1], q1);  atomicAdd(&ss[64 + c0 + 1], q2);
    __syncthreads();
    if (tid < 64) {
        atomicAdd(&s1[tid], ss[tid]);
        atomicAdd(&s2[tid], ss[64 + tid]);
    }
}

// ---------------- final layer aggregation (F=16, fp16 gather, no BN) -------
__global__ void k_agg16(const float* __restrict__ Ys, const __half* __restrict__ Yh,
                        const float* __restrict__ bias, float* __restrict__ O, int M)
{
    int tid = threadIdx.x, lane = tid & 31, w = tid >> 5;
    bool act = lane < 16;
    float b = act ? bias[lane] : 0.f;
    for (int v = blockIdx.x * 8 + w; v < M; v += gridDim.x * 8) {
        int beg = g_rowptr[v], end = g_rowptr[v + 1];
        float a = 0.f;
        for (int e = beg; e < end; e++) {
            int s = g_colidx[e];
            if (act) a += __half2float(Yh[(size_t)s * 16 + lane]);
        }
        if (act) {
            float ys = Ys[(size_t)v * 16 + lane];
            O[(size_t)v * 16 + lane] = fmaf(a, g_deginv[v], ys) + b;
        }
    }
}

// ---------------- launch ----------------
static constexpr int smem_mma(int K) { return 2 * 8 * (K / 16) * 32 * 16; }

extern "C" void kernel_launch(void* const* d_in, const int* in_sizes, int n_in,
                              void* d_out, int out_size)
{
    const float* x   = (const float*)d_in[0];
    const int*   src = (const int*)d_in[1];
    const int*   dst = (const int*)d_in[2];
    const float* Ws1 = (const float*)d_in[3];
    const float* Wn1 = (const float*)d_in[4];
    const float* b1  = (const float*)d_in[5];
    const float* g1  = (const float*)d_in[6];
    const float* be1 = (const float*)d_in[7];
    const float* Ws2 = (const float*)d_in[8];
    const float* Wn2 = (const float*)d_in[9];
    const float* b2  = (const float*)d_in[10];
    const float* g2  = (const float*)d_in[11];
    const float* be2 = (const float*)d_in[12];
    const float* Ws3 = (const float*)d_in[13];
    const float* Wn3 = (const float*)d_in[14];
    const float* b3  = (const float*)d_in[15];
    const float* g3  = (const float*)d_in[16];
    const float* be3 = (const float*)d_in[17];
    const float* Ws4 = (const float*)d_in[18];
    const float* Wn4 = (const float*)d_in[19];
    const float* b4  = (const float*)d_in[20];
    float* out = (float*)d_out;

    float *Ysp, *Hp, *st1, *st2;
    __half* Yhp;
    uint4* Bfp;
    cudaGetSymbolAddress((void**)&Ysp, g_Ys);
    cudaGetSymbolAddress((void**)&Yhp, g_Yh);
    cudaGetSymbolAddress((void**)&Hp,  g_H);
    cudaGetSymbolAddress((void**)&st1, g_stat1);
    cudaGetSymbolAddress((void**)&st2, g_stat2);
    cudaGetSymbolAddress((void**)&Bfp, g_Bf);

    const int EB = (NE + 255) / 256;
    const int GB = (NN + 127) / 128;
    const int AGG_GRID = 1184;

    cudaFuncSetAttribute(k_mma<128, 128, false, false>,
        cudaFuncAttributeMaxDynamicSharedMemorySize, smem_mma(128));
    cudaFuncSetAttribute(k_mma<64, 128, true, false>,
        cudaFuncAttributeMaxDynamicSharedMemorySize, smem_mma(64));
    cudaFuncSetAttribute(k_mma<64, 128, true, true>,
        cudaFuncAttributeMaxDynamicSharedMemorySize, smem_mma(64));
    cudaFuncSetAttribute(k_mma<64, 32, true, true>,
        cudaFuncAttributeMaxDynamicSharedMemorySize, smem_mma(64));

    // setup: stat/count zeroing, weight fragment packing, CSC build
    k_init<<<NBLK, 256>>>();
    k_bpack_all<<<34, 256>>>(Ws1, Wn1, Ws2, Wn2, Ws3, Wn3, Ws4, Wn4);
    k_hist<<<EB, 256>>>(dst);
    k_scan_block<<<NBLK, 256>>>();
    k_scan_tops<<<1, 512>>>(NBLK);
    k_scan_add<<<NBLK, 256>>>();
    k_fill<<<EB, 256>>>(src, dst);

    // layer 1: SAGE(128->64); BN1 stats accumulated in agg, applied in GEMM2
    k_mma<128, 128, false, false><<<GB, 256, smem_mma(128)>>>(
        x, Bfp, Ysp, Yhp, nullptr, nullptr, nullptr, nullptr, NN);
    k_agg64<<<AGG_GRID, 256>>>(Ysp, (const __half2*)Yhp, b1, Hp, st1, st2, NN);

    // layer 2: input = BN1(h1)
    k_mma<64, 128, true, false><<<GB, 256, smem_mma(64)>>>(
        Hp, Bfp + 4096, Ysp, Yhp, st1, st2, g1, be1, NN);
    k_agg64<<<AGG_GRID, 256>>>(Ysp, (const __half2*)Yhp, b2, Hp, st1 + 64, st2 + 64, NN);

    // layer 3: input = relu(BN2(h2))
    k_mma<64, 128, true, true><<<GB, 256, smem_mma(64)>>>(
        Hp, Bfp + 6144, Ysp, Yhp, st1 + 64, st2 + 64, g2, be2, NN);
    k_agg64<<<AGG_GRID, 256>>>(Ysp, (const __half2*)Yhp, b3, Hp, st1 + 128, st2 + 128, NN);

    // layer 4: SAGE(64->16), input = relu(BN3(h3))
    k_mma<64, 32, true, true><<<GB, 256, smem_mma(64)>>>(
        Hp, Bfp + 8192, Ysp, Yhp, st1 + 128, st2 + 128, g3, be3, NN);
    k_agg16<<<AGG_GRID, 256>>>(Ysp, Yhp, b4, out, NN);
}